// round 7
// baseline (speedup 1.0000x reference)
#include <cuda_runtime.h>
#include <cuda_bf16.h>
#include <cstdint>

typedef uint32_t u32;

#define BATCHN 131072
#define MROWS  128
#define NBLOCKS (BATCHN / MROWS)
#define TPB 256

// smem: 8 weight tiles (B-frag packed, 16KB each) + biases + true_vec
#define OFF_W    0
#define W_TILE   16384
#define OFF_BIAS 131072
#define OFF_TV   132608
#define SMEM_BYTES 132864

extern __shared__ char smc[];

// m16n8k16 row.col f32.bf16.bf16.f32
static __device__ __forceinline__ void mma_bf16(float* c, const u32* a, u32 b0, u32 b1) {
    asm volatile("mma.sync.aligned.m16n8k16.row.col.f32.bf16.bf16.f32 "
        "{%0,%1,%2,%3},{%4,%5,%6,%7},{%8,%9},{%0,%1,%2,%3};"
        : "+f"(c[0]), "+f"(c[1]), "+f"(c[2]), "+f"(c[3])
        : "r"(a[0]), "r"(a[1]), "r"(a[2]), "r"(a[3]), "r"(b0), "r"(b1));
}

static __device__ __forceinline__ u32 pack2(__nv_bfloat16 a, __nv_bfloat16 b) {
    __nv_bfloat162 t(a, b);
    return *reinterpret_cast<u32*>(&t);
}
static __device__ __forceinline__ void split(float v, __nv_bfloat16& h, __nv_bfloat16& l) {
    h = __float2bfloat16(v);
    l = __float2bfloat16(v - __bfloat162float(h));
}
// split a float2 into packed hi / packed lo
static __device__ __forceinline__ void splitpk(float2 v, u32& hp, u32& lp) {
    __nv_bfloat16 h0, l0, h1, l1;
    split(v.x, h0, l0); split(v.y, h1, l1);
    hp = pack2(h0, h1); lp = pack2(l0, l1);
}
static __device__ __forceinline__ float lrelu(float v) {
    return v > 0.f ? v : 0.01f * v;
}

// A-fragments for a 16x64 activation tile: 4 ktiles x 4 regs, hi + lo
struct Frag { u32 h[16]; u32 l[16]; };

// C += X @ Wtile  (64x64 unit, 3-pass bf16 emulation)
static __device__ __forceinline__ void gemm_unit(float C[32], const Frag& X,
                                                 const char* wt, int lane) {
#pragma unroll
    for (int kt = 0; kt < 4; kt++) {
#pragma unroll
        for (int nt = 0; nt < 8; nt++) {
            uint4 B = *(const uint4*)(wt + ((size_t)(kt * 8 + nt) * 32 + lane) * 16);
            mma_bf16(C + nt * 4, X.h + kt * 4, B.x, B.y);   // Ahi*Bhi
            mma_bf16(C + nt * 4, X.h + kt * 4, B.z, B.w);   // Ahi*Blo
            mma_bf16(C + nt * 4, X.l + kt * 4, B.x, B.y);   // Alo*Bhi
        }
    }
}

static __device__ __forceinline__ void zeroC(float C[32]) {
#pragma unroll
    for (int i = 0; i < 32; i++) C[i] = 0.f;
}

// C (+bias, opt. leaky-relu) -> A-frags of Y. C-frag cols map 1:1 onto A-frag k's.
static __device__ __forceinline__ void epi(const float C[32], const float* bias,
                                           bool relu, Frag& Y, int lane) {
    const int cb = (lane & 3) * 2;
#pragma unroll
    for (int nt = 0; nt < 8; nt++) {
        const float bb0 = bias[8 * nt + cb], bb1 = bias[8 * nt + cb + 1];
        float v0 = C[nt * 4 + 0] + bb0, v1 = C[nt * 4 + 1] + bb1;
        float v2 = C[nt * 4 + 2] + bb0, v3 = C[nt * 4 + 3] + bb1;
        if (relu) { v0 = lrelu(v0); v1 = lrelu(v1); v2 = lrelu(v2); v3 = lrelu(v3); }
        const int o = (nt >> 1) * 4 + (nt & 1) * 2;
        splitpk(make_float2(v0, v1), Y.h[o], Y.l[o]);         // row r0
        splitpk(make_float2(v2, v3), Y.h[o + 1], Y.l[o + 1]); // row r0+8
    }
}

// gather one embedding row pair straight into A-frag registers
static __device__ __forceinline__ void gather(Frag& Y, const float* e0,
                                              const float* e1, int q) {
#pragma unroll
    for (int kt = 0; kt < 4; kt++) {
        float2 a = ((const float2*)e0)[8 * kt + q];
        float2 b = ((const float2*)e1)[8 * kt + q];
        float2 c = ((const float2*)e0)[8 * kt + q + 4];
        float2 d = ((const float2*)e1)[8 * kt + q + 4];
        splitpk(a, Y.h[kt * 4 + 0], Y.l[kt * 4 + 0]);
        splitpk(b, Y.h[kt * 4 + 1], Y.l[kt * 4 + 1]);
        splitpk(c, Y.h[kt * 4 + 2], Y.l[kt * 4 + 2]);
        splitpk(d, Y.h[kt * 4 + 3], Y.l[kt * 4 + 3]);
    }
}

#define WT(i) (smc + OFF_W + (i) * W_TILE)

// NOT: Y = mlp1(X) with tiles (t1,t2), biases bs
static __device__ __forceinline__ void mlp_not(const Frag& X, Frag& Y,
                                               const float* bs, int lane) {
    float C[32]; Frag H;
    zeroC(C);
    gemm_unit(C, X, WT(0), lane);
    epi(C, bs + 0, true, H, lane);
    zeroC(C);
    gemm_unit(C, H, WT(1), lane);
    epi(C, bs + 64, false, Y, lane);
}

// AND/OR: Y = mlp2(concat(X1,X2)) with tiles (ta,tb,t2)
static __device__ __forceinline__ void mlp2(const Frag& X1, const Frag& X2, Frag& Y,
                                            const char* ta, const char* tb,
                                            const char* t2, const float* bs, int lane) {
    float C[32]; Frag H;
    zeroC(C);
    gemm_unit(C, X1, ta, lane);
    gemm_unit(C, X2, tb, lane);
    epi(C, bs + 0, true, H, lane);
    zeroC(C);
    gemm_unit(C, H, t2, lane);
    epi(C, bs + 64, false, Y, lane);
}

// final OR + cosine epilogue, writes 2 outputs per participating lane
static __device__ __forceinline__ void mlp2_cos(const Frag& X1, const Frag& X2,
                                                const char* ta, const char* tb,
                                                const char* t2, const float* bs,
                                                const float* tvs, float tvd,
                                                float* out, int g0, int g1, int lane) {
    float C[32]; Frag H;
    zeroC(C);
    gemm_unit(C, X1, ta, lane);
    gemm_unit(C, X2, tb, lane);
    epi(C, bs + 0, true, H, lane);
    zeroC(C);
    gemm_unit(C, H, t2, lane);
    const float* b2 = bs + 64;
    const int cb = (lane & 3) * 2;
    float nu0 = 0.f, nr0 = 0.f, nu1 = 0.f, nr1 = 0.f;
#pragma unroll
    for (int nt = 0; nt < 8; nt++) {
        const int c0 = 8 * nt + cb;
        const float bb0 = b2[c0], bb1 = b2[c0 + 1];
        const float t0 = tvs[c0], t1 = tvs[c0 + 1];
        float v0 = C[nt * 4 + 0] + bb0, v1 = C[nt * 4 + 1] + bb1;
        float v2 = C[nt * 4 + 2] + bb0, v3 = C[nt * 4 + 3] + bb1;
        nu0 = fmaf(v0, t0, fmaf(v1, t1, nu0));
        nr0 = fmaf(v0, v0, fmaf(v1, v1, nr0));
        nu1 = fmaf(v2, t0, fmaf(v3, t1, nu1));
        nr1 = fmaf(v2, v2, fmaf(v3, v3, nr1));
    }
#pragma unroll
    for (int off = 1; off <= 2; off <<= 1) {
        nu0 += __shfl_xor_sync(~0u, nu0, off);
        nr0 += __shfl_xor_sync(~0u, nr0, off);
        nu1 += __shfl_xor_sync(~0u, nu1, off);
        nr1 += __shfl_xor_sync(~0u, nr1, off);
    }
    if ((lane & 3) == 0) {
        out[g0] = nu0 / (fmaxf(sqrtf(nr0), 1e-8f) * tvd) * 10.0f;
        out[g1] = nu1 / (fmaxf(sqrtf(nr1), 1e-8f) * tvd) * 10.0f;
    }
}

__global__ void __launch_bounds__(TPB, 1)
logicnet_kernel(const int* __restrict__ seq,
                const int* __restrict__ pos_t,
                const int* __restrict__ neg_t,
                const float* __restrict__ item_embed,
                const float* __restrict__ g_tv,
                const float* __restrict__ nW1, const float* __restrict__ nb1,
                const float* __restrict__ nW2, const float* __restrict__ nb2,
                const float* __restrict__ aW1, const float* __restrict__ ab1,
                const float* __restrict__ aW2, const float* __restrict__ ab2,
                const float* __restrict__ oW1, const float* __restrict__ ob1,
                const float* __restrict__ oW2, const float* __restrict__ ob2,
                float* __restrict__ out) {
    const int tid = threadIdx.x, w = tid >> 5, lane = tid & 31;

    // ---- stage weights into B-fragment-packed smem (hi/lo interleaved uint4) ----
    {
        const float* wsrc[8] = { nW1, nW2, aW1, aW1 + 4096, aW2, oW1, oW1 + 4096, oW2 };
#pragma unroll 1
        for (int e = tid; e < 8192; e += TPB) {
            const int t = e >> 10, rem = e & 1023, ktnt = rem >> 5, ln = rem & 31;
            const int k0 = (ktnt >> 3) * 16 + (ln & 3) * 2;
            const int n  = (ktnt & 7) * 8 + (ln >> 2);
            const float* s = wsrc[t];
            const float w00 = s[(k0)     * 64 + n], w01 = s[(k0 + 1) * 64 + n];
            const float w10 = s[(k0 + 8) * 64 + n], w11 = s[(k0 + 9) * 64 + n];
            u32 bh0, bl0, bh1, bl1;
            splitpk(make_float2(w00, w01), bh0, bl0);
            splitpk(make_float2(w10, w11), bh1, bl1);
            *(uint4*)(smc + OFF_W + (size_t)t * W_TILE + ((size_t)ktnt * 32 + ln) * 16) =
                make_uint4(bh0, bh1, bl0, bl1);
        }
        float* sb = (float*)(smc + OFF_BIAS);
        if (tid < 64) {
            sb[tid]       = nb1[tid]; sb[64 + tid]  = nb2[tid];
            sb[128 + tid] = ab1[tid]; sb[192 + tid] = ab2[tid];
            sb[256 + tid] = ob1[tid]; sb[320 + tid] = ob2[tid];
            ((float*)(smc + OFF_TV))[tid] = g_tv[tid];
        }
    }
    __syncthreads();

    const float* BS  = (const float*)(smc + OFF_BIAS);
    const float* tvs = (const float*)(smc + OFF_TV);
    float t2 = 0.f;
#pragma unroll
    for (int c = 0; c < 64; c++) t2 = fmaf(tvs[c], tvs[c], t2);
    const float tvd = fmaxf(sqrtf(t2), 1e-8f);

    // this warp's two row groups and quad column
    const int g0 = blockIdx.x * MROWS + w * 16 + (lane >> 2);
    const int g1 = g0 + 8;
    const int q  = lane & 3;

    Frag b0, b1, b2;

#define EMB(id) (item_embed + (size_t)(id) * 64)
#define GATHER_SEQ(Y, p) gather(Y, EMB(seq[g0 * 5 + (p)]), EMB(seq[g1 * 5 + (p)]), q)

    GATHER_SEQ(b0, 1);                                           // e(seq1)
    mlp_not(b0, b0, BS + 0, lane);                               // n1
    GATHER_SEQ(b1, 0);                                           // e(seq0)
    mlp2(b1, b0, b0, WT(2), WT(3), WT(4), BS + 128, lane);       // int5 = AND(e0, n1)
    GATHER_SEQ(b1, 2);                                           // e(seq2)
    GATHER_SEQ(b2, 3);                                           // e(seq3)
    mlp2(b1, b2, b1, WT(5), WT(6), WT(7), BS + 256, lane);       // int6 = OR(e2, e3)
    mlp2(b0, b1, b0, WT(2), WT(3), WT(4), BS + 128, lane);       // int7 = AND(int5, int6)
    mlp_not(b0, b0, BS + 0, lane);                               // NOT(int7)
    GATHER_SEQ(b1, 4);                                           // e(seq4)
    mlp2(b0, b1, b0, WT(5), WT(6), WT(7), BS + 256, lane);       // out = OR(n7, e4)
    mlp_not(b0, b0, BS + 0, lane);                               // enc_not
    gather(b1, EMB(pos_t[g0]), EMB(pos_t[g1]), q);               // pos_e
    mlp2_cos(b0, b1, WT(5), WT(6), WT(7), BS + 256,
             tvs, tvd, out, g0, g1, lane);                       // encoded_pos
    gather(b1, EMB(neg_t[g0]), EMB(neg_t[g1]), q);               // neg_e
    mlp2_cos(b0, b1, WT(5), WT(6), WT(7), BS + 256,
             tvs, tvd, out + BATCHN, g0, g1, lane);              // encoded_neg
}

extern "C" void kernel_launch(void* const* d_in, const int* in_sizes, int n_in,
                              void* d_out, int out_size) {
    (void)in_sizes; (void)n_in; (void)out_size;
    cudaFuncSetAttribute(logicnet_kernel,
                         cudaFuncAttributeMaxDynamicSharedMemorySize, SMEM_BYTES);
    logicnet_kernel<<<NBLOCKS, TPB, SMEM_BYTES>>>(
        (const int*)d_in[0], (const int*)d_in[1], (const int*)d_in[2],
        (const float*)d_in[3], (const float*)d_in[4],
        (const float*)d_in[5], (const float*)d_in[6],
        (const float*)d_in[7], (const float*)d_in[8],
        (const float*)d_in[9], (const float*)d_in[10],
        (const float*)d_in[11], (const float*)d_in[12],
        (const float*)d_in[13], (const float*)d_in[14],
        (const float*)d_in[15], (const float*)d_in[16],
        (float*)d_out);
}

// round 8
// speedup vs baseline: 2.3722x; 2.3722x over previous
#include <cuda_runtime.h>
#include <cuda_bf16.h>
#include <cstdint>

typedef uint32_t u32;

#define BATCHN 131072
#define MROWS  128
#define NBLOCKS (BATCHN / MROWS)
#define TPB 256

// smem byte layout
#define OFF_W    0            // 8 weight tiles, B-frag packed, 16KB each
#define W_TILE   16384
#define OFF_A    131072       // 8 warps x 3 activation buffers x 4KB (hi 2K + lo 2K)
#define ABUF     4096
#define OFF_BIAS 229376       // 6 x 64 fp32
#define OFF_TV   230912       // 64 fp32
#define SMEM_BYTES 231168

extern __shared__ char smc[];

// m16n8k16 row.col f32.bf16.bf16.f32
static __device__ __forceinline__ void mma_bf16(float* c, const u32* a, u32 b0, u32 b1) {
    asm volatile("mma.sync.aligned.m16n8k16.row.col.f32.bf16.bf16.f32 "
        "{%0,%1,%2,%3},{%4,%5,%6,%7},{%8,%9},{%0,%1,%2,%3};"
        : "+f"(c[0]), "+f"(c[1]), "+f"(c[2]), "+f"(c[3])
        : "r"(a[0]), "r"(a[1]), "r"(a[2]), "r"(a[3]), "r"(b0), "r"(b1));
}

static __device__ __forceinline__ u32 pack2(__nv_bfloat16 a, __nv_bfloat16 b) {
    __nv_bfloat162 t(a, b);
    return *reinterpret_cast<u32*>(&t);
}
static __device__ __forceinline__ void split(float v, __nv_bfloat16& h, __nv_bfloat16& l) {
    h = __float2bfloat16(v);
    l = __float2bfloat16(v - __bfloat162float(h));
}
static __device__ __forceinline__ void splitpk(float2 v, u32& hp, u32& lp) {
    __nv_bfloat16 h0, l0, h1, l1;
    split(v.x, h0, l0); split(v.y, h1, l1);
    hp = pack2(h0, h1); lp = pack2(l0, l1);
}
static __device__ __forceinline__ float lrelu(float v) {
    return v > 0.f ? v : 0.01f * v;
}
static __device__ __forceinline__ void zeroC(float C[32]) {
#pragma unroll
    for (int i = 0; i < 32; i++) C[i] = 0.f;
}

// ---- C += X(smem frag-packed) @ Wtile : 64x64 unit, 3-pass bf16 emulation ----
static __device__ __forceinline__ void gemm_unit(float C[32], const char* abuf,
                                                 const char* wt, int lane) {
#pragma unroll 1
    for (int kt = 0; kt < 4; kt++) {
        const uint4 Ah = *(const uint4*)(abuf + ((kt * 32 + lane) << 4));
        const uint4 Al = *(const uint4*)(abuf + 2048 + ((kt * 32 + lane) << 4));
#pragma unroll
        for (int nt = 0; nt < 8; nt++) {
            const uint4 B = *(const uint4*)(wt + (((kt * 8 + nt) * 32 + lane) << 4));
            mma_bf16(C + nt * 4, (const u32*)&Ah, B.x, B.y);   // Ahi*Bhi
            mma_bf16(C + nt * 4, (const u32*)&Ah, B.z, B.w);   // Ahi*Blo
            mma_bf16(C + nt * 4, (const u32*)&Al, B.x, B.y);   // Alo*Bhi
        }
    }
}

// ---- C (+bias, opt lrelu) -> frag-packed smem buffer (lane-private) ----
static __device__ __forceinline__ void epi_store(const float C[32], const float* bias,
                                                 bool relu, char* dst, int lane) {
    const int cb = (lane & 3) * 2;
    u32 h[16], l[16];
#pragma unroll
    for (int nt = 0; nt < 8; nt++) {
        const float bb0 = bias[8 * nt + cb], bb1 = bias[8 * nt + cb + 1];
        float v0 = C[nt * 4 + 0] + bb0, v1 = C[nt * 4 + 1] + bb1;
        float v2 = C[nt * 4 + 2] + bb0, v3 = C[nt * 4 + 3] + bb1;
        if (relu) { v0 = lrelu(v0); v1 = lrelu(v1); v2 = lrelu(v2); v3 = lrelu(v3); }
        const int o = (nt >> 1) * 4 + (nt & 1) * 2;
        splitpk(make_float2(v0, v1), h[o], l[o]);
        splitpk(make_float2(v2, v3), h[o + 1], l[o + 1]);
    }
#pragma unroll
    for (int kt = 0; kt < 4; kt++) {
        *(uint4*)(dst + ((kt * 32 + lane) << 4)) =
            make_uint4(h[4 * kt], h[4 * kt + 1], h[4 * kt + 2], h[4 * kt + 3]);
        *(uint4*)(dst + 2048 + ((kt * 32 + lane) << 4)) =
            make_uint4(l[4 * kt], l[4 * kt + 1], l[4 * kt + 2], l[4 * kt + 3]);
    }
}

// ---- gather embedding rows straight into frag-packed smem (lane-private) ----
static __device__ __forceinline__ void gather_store(char* dst, const float* e0,
                                                    const float* e1, int q, int lane) {
#pragma unroll
    for (int kt = 0; kt < 4; kt++) {
        float2 a = ((const float2*)e0)[8 * kt + q];
        float2 b = ((const float2*)e1)[8 * kt + q];
        float2 c = ((const float2*)e0)[8 * kt + q + 4];
        float2 d = ((const float2*)e1)[8 * kt + q + 4];
        u32 h0, l0, h1, l1, h2, l2, h3, l3;
        splitpk(a, h0, l0); splitpk(b, h1, l1);
        splitpk(c, h2, l2); splitpk(d, h3, l3);
        *(uint4*)(dst + ((kt * 32 + lane) << 4))        = make_uint4(h0, h1, h2, h3);
        *(uint4*)(dst + 2048 + ((kt * 32 + lane) << 4)) = make_uint4(l0, l1, l2, l3);
    }
}

#define WT(i) (smc + OFF_W + (i) * W_TILE)

// NOT mlp: dst = mlp(src) using tiles w1t/w1t+1
static __device__ __noinline__ void mlp_not(char* src, char* hid, char* dst,
                                            const float* bs, int lane) {
    float C[32];
    zeroC(C);
    gemm_unit(C, src, WT(0), lane);
    epi_store(C, bs, true, hid, lane);
    zeroC(C);
    gemm_unit(C, hid, WT(1), lane);
    epi_store(C, bs + 64, false, dst, lane);
}

// AND/OR mlp: dst = mlp(concat(x1,x2)); tiles (ta, ta+1, ta+2) = (W1a, W1b, W2)
static __device__ __noinline__ void mlp2(char* x1, char* x2, char* hid, char* dst,
                                         const char* ta, const float* bs, int lane) {
    float C[32];
    zeroC(C);
    gemm_unit(C, x1, ta, lane);
    gemm_unit(C, x2, ta + W_TILE, lane);
    epi_store(C, bs, true, hid, lane);
    zeroC(C);
    gemm_unit(C, hid, ta + 2 * W_TILE, lane);
    epi_store(C, bs + 64, false, dst, lane);
}

// final OR + cosine epilogue
static __device__ __noinline__ void mlp2_cos(char* x1, char* x2, char* hid,
                                             const char* ta, const float* bs,
                                             const float* tvs, float tvd,
                                             float* outp, int g0, int g1, int lane) {
    float C[32];
    zeroC(C);
    gemm_unit(C, x1, ta, lane);
    gemm_unit(C, x2, ta + W_TILE, lane);
    epi_store(C, bs, true, hid, lane);
    zeroC(C);
    gemm_unit(C, hid, ta + 2 * W_TILE, lane);
    const float* b2 = bs + 64;
    const int cb = (lane & 3) * 2;
    float nu0 = 0.f, nr0 = 0.f, nu1 = 0.f, nr1 = 0.f;
#pragma unroll
    for (int nt = 0; nt < 8; nt++) {
        const int c0 = 8 * nt + cb;
        const float bb0 = b2[c0], bb1 = b2[c0 + 1];
        const float t0 = tvs[c0], t1 = tvs[c0 + 1];
        float v0 = C[nt * 4 + 0] + bb0, v1 = C[nt * 4 + 1] + bb1;
        float v2 = C[nt * 4 + 2] + bb0, v3 = C[nt * 4 + 3] + bb1;
        nu0 = fmaf(v0, t0, fmaf(v1, t1, nu0));
        nr0 = fmaf(v0, v0, fmaf(v1, v1, nr0));
        nu1 = fmaf(v2, t0, fmaf(v3, t1, nu1));
        nr1 = fmaf(v2, v2, fmaf(v3, v3, nr1));
    }
#pragma unroll
    for (int off = 1; off <= 2; off <<= 1) {
        nu0 += __shfl_xor_sync(~0u, nu0, off);
        nr0 += __shfl_xor_sync(~0u, nr0, off);
        nu1 += __shfl_xor_sync(~0u, nu1, off);
        nr1 += __shfl_xor_sync(~0u, nr1, off);
    }
    if ((lane & 3) == 0) {
        outp[g0] = nu0 / (fmaxf(sqrtf(nr0), 1e-8f) * tvd) * 10.0f;
        outp[g1] = nu1 / (fmaxf(sqrtf(nr1), 1e-8f) * tvd) * 10.0f;
    }
}

__global__ void __launch_bounds__(TPB, 1)
logicnet_kernel(const int* __restrict__ seq,
                const int* __restrict__ pos_t,
                const int* __restrict__ neg_t,
                const float* __restrict__ item_embed,
                const float* __restrict__ g_tv,
                const float* __restrict__ nW1, const float* __restrict__ nb1,
                const float* __restrict__ nW2, const float* __restrict__ nb2,
                const float* __restrict__ aW1, const float* __restrict__ ab1,
                const float* __restrict__ aW2, const float* __restrict__ ab2,
                const float* __restrict__ oW1, const float* __restrict__ ob1,
                const float* __restrict__ oW2, const float* __restrict__ ob2,
                float* __restrict__ out) {
    const int tid = threadIdx.x, w = tid >> 5, lane = tid & 31;

    // ---- stage weights into B-fragment-packed smem (hi,hi,lo,lo per uint4) ----
    {
        const float* wsrc[8] = { nW1, nW2, aW1, aW1 + 4096, aW2, oW1, oW1 + 4096, oW2 };
#pragma unroll 1
        for (int e = tid; e < 8192; e += TPB) {
            const int t = e >> 10, rem = e & 1023, ktnt = rem >> 5, ln = rem & 31;
            const int k0 = (ktnt >> 3) * 16 + (ln & 3) * 2;
            const int n  = (ktnt & 7) * 8 + (ln >> 2);
            const float* s = wsrc[t];
            const float w00 = s[(k0)     * 64 + n], w01 = s[(k0 + 1) * 64 + n];
            const float w10 = s[(k0 + 8) * 64 + n], w11 = s[(k0 + 9) * 64 + n];
            u32 bh0, bl0, bh1, bl1;
            splitpk(make_float2(w00, w01), bh0, bl0);
            splitpk(make_float2(w10, w11), bh1, bl1);
            *(uint4*)(smc + OFF_W + (size_t)t * W_TILE + ((size_t)ktnt * 32 + ln) * 16) =
                make_uint4(bh0, bh1, bl0, bl1);
        }
        float* sb = (float*)(smc + OFF_BIAS);
        if (tid < 64) {
            sb[tid]       = nb1[tid]; sb[64 + tid]  = nb2[tid];
            sb[128 + tid] = ab1[tid]; sb[192 + tid] = ab2[tid];
            sb[256 + tid] = ob1[tid]; sb[320 + tid] = ob2[tid];
            ((float*)(smc + OFF_TV))[tid] = g_tv[tid];
        }
    }
    __syncthreads();

    const float* BS  = (const float*)(smc + OFF_BIAS);
    const float* tvs = (const float*)(smc + OFF_TV);
    float t2 = 0.f;
#pragma unroll
    for (int c = 0; c < 64; c++) t2 = fmaf(tvs[c], tvs[c], t2);
    const float tvd = fmaxf(sqrtf(t2), 1e-8f);

    // this warp's rows and quad column; per-warp activation buffers
    const int g0 = blockIdx.x * MROWS + w * 16 + (lane >> 2);
    const int g1 = g0 + 8;
    const int q  = lane & 3;
    char* B0 = smc + OFF_A + (w * 3 + 0) * ABUF;
    char* B1 = smc + OFF_A + (w * 3 + 1) * ABUF;
    char* B2 = smc + OFF_A + (w * 3 + 2) * ABUF;

#define EMB(id) (item_embed + (size_t)(id) * 64)
#define GSEQ(dst, p) gather_store(dst, EMB(seq[g0 * 5 + (p)]), EMB(seq[g1 * 5 + (p)]), q, lane)

    GSEQ(B0, 1);                                             // e(seq1)
    mlp_not(B0, B1, B0, BS + 0, lane);                       // n1 -> B0
    GSEQ(B1, 0);                                             // e(seq0)
    mlp2(B1, B0, B2, B0, WT(2), BS + 128, lane);             // int5 = AND(e0,n1) -> B0
    GSEQ(B1, 2);                                             // e(seq2)
    GSEQ(B2, 3);                                             // e(seq3)
    mlp2(B1, B2, B1, B1, WT(5), BS + 256, lane);             // int6 = OR(e2,e3) -> B1
    mlp2(B0, B1, B2, B0, WT(2), BS + 128, lane);             // int7 = AND(int5,int6) -> B0
    mlp_not(B0, B2, B0, BS + 0, lane);                       // NOT(int7) -> B0
    GSEQ(B1, 4);                                             // e(seq4)
    mlp2(B0, B1, B2, B0, WT(5), BS + 256, lane);             // out = OR(n7,e4) -> B0
    mlp_not(B0, B1, B0, BS + 0, lane);                       // enc_not -> B0
    gather_store(B1, EMB(pos_t[g0]), EMB(pos_t[g1]), q, lane);
    mlp2_cos(B0, B1, B2, WT(5), BS + 256, tvs, tvd, out, g0, g1, lane);
    gather_store(B1, EMB(neg_t[g0]), EMB(neg_t[g1]), q, lane);
    mlp2_cos(B0, B1, B2, WT(5), BS + 256, tvs, tvd, out + BATCHN, g0, g1, lane);
}

extern "C" void kernel_launch(void* const* d_in, const int* in_sizes, int n_in,
                              void* d_out, int out_size) {
    (void)in_sizes; (void)n_in; (void)out_size;
    cudaFuncSetAttribute(logicnet_kernel,
                         cudaFuncAttributeMaxDynamicSharedMemorySize, SMEM_BYTES);
    logicnet_kernel<<<NBLOCKS, TPB, SMEM_BYTES>>>(
        (const int*)d_in[0], (const int*)d_in[1], (const int*)d_in[2],
        (const float*)d_in[3], (const float*)d_in[4],
        (const float*)d_in[5], (const float*)d_in[6],
        (const float*)d_in[7], (const float*)d_in[8],
        (const float*)d_in[9], (const float*)d_in[10],
        (const float*)d_in[11], (const float*)d_in[12],
        (const float*)d_in[13], (const float*)d_in[14],
        (const float*)d_in[15], (const float*)d_in[16],
        (float*)d_out);
}